// round 13
// baseline (speedup 1.0000x reference)
#include <cuda_runtime.h>
#include <cuda_fp16.h>
#include <cstdint>

#define HID   128
#define MAXN  100000

// Static device scratch (allocation guards forbid cudaMalloc)
__device__ __half g_Ah[MAXN * HID];   // 25.6 MB  fp16 table A
__device__ __half g_Bh[MAXN * HID];   // 25.6 MB  fp16 table B

// ---------------------------------------------------------------------------
// GEMM precompute via mma.sync (HMMA, PTX-portable):
//   half 0: g_Ah[tile] = half( z_src_tile[128x128] @ W1top + b1 )
//   half 1: g_Bh[tile] = half( z_dst_tile[128x128] @ W1bot )
// CTA: 256 thr (8 warps), tile M=128,N=128,K=128.
// Warp tile 32x64: 2 Mtiles x 8 Ntiles of m16n8k16, 8 k-steps.
// smem: sA z-half [128][136], sB W^T-half [128][136] (padded, conflict-free
// for fragment loads). W transposed+converted in-kernel from fp32 W1 (L2-hot),
// overlapped with the z-tile global loads — no separate wprep launch.
// ---------------------------------------------------------------------------
#define SSTR 136   // smem row stride in halfs (272 B = 17*16, uint4-aligned)

__global__ __launch_bounds__(256) void gemm_kernel(
    const float* __restrict__ zsrc, const float* __restrict__ zdst,
    const float* __restrict__ W1, const float* __restrict__ b1,
    int nNodes, int nT)
{
    extern __shared__ __half smem[];
    __half* sA = smem;              // [128][SSTR]
    __half* sB = smem + 128 * SSTR; // [128][SSTR]  (sB[n][k] = W1[half*128+k][n])

    const int half = (blockIdx.x >= (unsigned)nT) ? 1 : 0;
    const int t    = blockIdx.x - half * nT;
    const float* z = half ? zdst : zsrc;
    __half*    tab = half ? g_Bh : g_Ah;

    const int tid  = threadIdx.x;
    const int wid  = tid >> 5;
    const int lane = tid & 31;
    const int grp  = lane >> 2;     // 0..7
    const int tig  = lane & 3;      // 0..3

    // ---- W^T convert+transpose into sB (reads fp32 W1, L2-resident) ----
    {
        const float* Wh = W1 + half * HID * HID;   // [k][n] row-major
        #pragma unroll 8
        for (int i = tid; i < HID * HID / 2; i += 256) {
            // i enumerates (k, n-pair): coalesced float2 read, 2 scalar writes
            int k = i >> 6, n0 = (i & 63) * 2;
            float2 v = *(const float2*)(Wh + k * HID + n0);
            sB[(n0 + 0) * SSTR + k] = __float2half(v.x);
            sB[(n0 + 1) * SSTR + k] = __float2half(v.y);
        }
    }
    // ---- load z tile fp32 -> half into sA: [m][k], stride SSTR ----
    {
        const float4* zg = (const float4*)z;
        const size_t base4 = (size_t)t * 4096;        // 128 rows * 32 float4
        const size_t lim4  = (size_t)nNodes * 32;
        #pragma unroll 4
        for (int i = tid; i < 4096; i += 256) {
            float4 v = make_float4(0.f, 0.f, 0.f, 0.f);
            size_t g = base4 + i;
            if (g < lim4) v = zg[g];
            int row = i >> 5, c0 = (i & 31) * 4;
            __half2 h0 = __floats2half2_rn(v.x, v.y);
            __half2 h1 = __floats2half2_rn(v.z, v.w);
            *(uint32_t*)(sA + row * SSTR + c0)     = *(uint32_t*)&h0;
            *(uint32_t*)(sA + row * SSTR + c0 + 2) = *(uint32_t*)&h1;
        }
    }
    __syncthreads();

    const int m_base = (wid >> 1) * 32;   // 4 M-quadrants
    const int n_base = (wid & 1) * 64;    // 2 N-halves

    float c[2][8][4];
    #pragma unroll
    for (int mt = 0; mt < 2; mt++)
        #pragma unroll
        for (int nt = 0; nt < 8; nt++)
            #pragma unroll
            for (int j = 0; j < 4; j++) c[mt][nt][j] = 0.f;

    #pragma unroll
    for (int ks = 0; ks < 8; ks++) {
        const int k0 = ks * 16;
        uint32_t a[2][4], b[8][2];
        #pragma unroll
        for (int mt = 0; mt < 2; mt++) {
            const __half* pr = sA + (m_base + mt * 16 + grp) * SSTR + k0 + tig * 2;
            a[mt][0] = *(const uint32_t*)pr;
            a[mt][1] = *(const uint32_t*)(pr + 8 * SSTR);
            a[mt][2] = *(const uint32_t*)(pr + 8);
            a[mt][3] = *(const uint32_t*)(pr + 8 * SSTR + 8);
        }
        #pragma unroll
        for (int nt = 0; nt < 8; nt++) {
            const __half* pb = sB + (n_base + nt * 8 + grp) * SSTR + k0 + tig * 2;
            b[nt][0] = *(const uint32_t*)pb;
            b[nt][1] = *(const uint32_t*)(pb + 8);
        }
        #pragma unroll
        for (int mt = 0; mt < 2; mt++)
            #pragma unroll
            for (int nt = 0; nt < 8; nt++)
                asm volatile(
                    "mma.sync.aligned.m16n8k16.row.col.f32.f16.f16.f32 "
                    "{%0,%1,%2,%3}, {%4,%5,%6,%7}, {%8,%9}, {%0,%1,%2,%3};"
                    : "+f"(c[mt][nt][0]), "+f"(c[mt][nt][1]),
                      "+f"(c[mt][nt][2]), "+f"(c[mt][nt][3])
                    : "r"(a[mt][0]), "r"(a[mt][1]), "r"(a[mt][2]), "r"(a[mt][3]),
                      "r"(b[nt][0]), "r"(b[nt][1]));
    }
    __syncthreads();    // done reading sA/sB; reuse sA as output stage

    // ---- epilogue: bias (half 0), fp16 pack, stage to sA [m][SSTR] ----
    #pragma unroll
    for (int nt = 0; nt < 8; nt++) {
        const int col = n_base + nt * 8 + tig * 2;
        float bx = 0.f, by = 0.f;
        if (half == 0) { bx = b1[col]; by = b1[col + 1]; }
        #pragma unroll
        for (int mt = 0; mt < 2; mt++) {
            const int r0 = m_base + mt * 16 + grp;
            __half2 h0 = __floats2half2_rn(c[mt][nt][0] + bx, c[mt][nt][1] + by);
            __half2 h1 = __floats2half2_rn(c[mt][nt][2] + bx, c[mt][nt][3] + by);
            *(uint32_t*)(sA + r0 * SSTR + col)       = *(uint32_t*)&h0;
            *(uint32_t*)(sA + (r0 + 8) * SSTR + col) = *(uint32_t*)&h1;
        }
    }
    __syncthreads();

    // ---- coalesced store: 2048 uint4 (128 rows x 16 uint4) ----
    {
        #pragma unroll 4
        for (int i = tid; i < 2048; i += 256) {
            int row = i >> 4, c8 = (i & 15) * 8;
            int node = t * 128 + row;
            if (node < nNodes)
                *(uint4*)(tab + (size_t)node * HID + c8) =
                    *(const uint4*)(sA + row * SSTR + c8);
        }
    }
}

// ---------------------------------------------------------------------------
// Edge kernel (exact round-11 winner): warp = 4 edges, 8 LANES PER EDGE
// (eg=lane>>3, cg=lane&7). COALESCED: lane cg reads uint4 [cg] and [cg+8] of
// the 16-uint4 row, so each LDG.128 instruction covers one contiguous 128B
// segment per edge (4 segments per instruction warp-wide). 3 shfl_xor(1,2,4)
// serve all 4 edges at once.
// ---------------------------------------------------------------------------
__global__ __launch_bounds__(256) void edge_kernel(
    const void* __restrict__ ps, const void* __restrict__ pd,
    const void* __restrict__ ns, const void* __restrict__ nd,
    const float* __restrict__ W2, const float* __restrict__ b2,
    float* __restrict__ out, int E2, int Eh, int nNodes)
{
    __shared__ int sF64;
    if (threadIdx.x == 0) {
        const long long* arrs[4] = {(const long long*)ps, (const long long*)pd,
                                    (const long long*)ns, (const long long*)nd};
        int step = (Eh / 2) / 8;
        if (step < 1) step = 1;
        int ok = 1;
        for (int a = 0; a < 4; a++)
            for (int j = 0; j < 8; j++) {
                long long v = arrs[a][(long long)j * step];
                if (v < 0 || v >= nNodes) ok = 0;
            }
        sF64 = ok;
    }
    __syncthreads();
    const int f64 = sF64;

    const int lane = threadIdx.x & 31;
    const int eg   = lane >> 3;     // which of 4 edges
    const int cg   = lane & 7;      // lane within edge group
    const int gw   = (blockIdx.x * blockDim.x + threadIdx.x) >> 5;
    const int nw   = (gridDim.x * blockDim.x) >> 5;

    // W2 slices: cols 8cg..8cg+7 (low half) and 64+8cg..64+8cg+7 (high half)
    const float4 w0 = ((const float4*)W2)[2 * cg];
    const float4 w1 = ((const float4*)W2)[2 * cg + 1];
    const float4 w2_ = ((const float4*)W2)[16 + 2 * cg];
    const float4 w3 = ((const float4*)W2)[17 + 2 * cg];
    const float  b2s = b2[0];
    const uint4* A4 = (const uint4*)g_Ah;   // row = 16 uint4 (256 B)
    const uint4* B4 = (const uint4*)g_Bh;
    const __half2 hz = __float2half2_rn(0.f);

    auto ldidx = [&](const void* p, int i) -> int {
        long long v = f64 ? ((const long long*)p)[i]
                          : (long long)((const int*)p)[i];
        if (v < 0) v = 0;
        if (v >= nNodes) v = nNodes - 1;
        return (int)v;
    };
    auto dot8 = [&](uint4 a, uint4 b, float4 wA, float4 wB) -> float {
        __half2 s0 = __hmax2(__hadd2(*(__half2*)&a.x, *(__half2*)&b.x), hz);
        __half2 s1 = __hmax2(__hadd2(*(__half2*)&a.y, *(__half2*)&b.y), hz);
        __half2 s2 = __hmax2(__hadd2(*(__half2*)&a.z, *(__half2*)&b.z), hz);
        __half2 s3 = __hmax2(__hadd2(*(__half2*)&a.w, *(__half2*)&b.w), hz);
        float2 f0 = __half22float2(s0);
        float2 f1 = __half22float2(s1);
        float2 f2 = __half22float2(s2);
        float2 f3 = __half22float2(s3);
        return f0.x*wA.x + f0.y*wA.y + f1.x*wA.z + f1.y*wA.w
             + f2.x*wB.x + f2.y*wB.y + f3.x*wB.z + f3.y*wB.w;
    };

    for (int base = gw * 4; base < E2; base += nw * 4) {
        int e = base + eg;
        int s = 0, d = 0;
        if (e < E2) {
            if (e < Eh) { s = ldidx(ps, e);      d = ldidx(pd, e); }
            else        { s = ldidx(ns, e - Eh); d = ldidx(nd, e - Eh); }
        }

        const size_t sr = (size_t)s * 16;
        const size_t dr = (size_t)d * 16;
        uint4 a0 = A4[sr + cg],     b0 = B4[dr + cg];       // contiguous 128B
        uint4 a1 = A4[sr + cg + 8], b1 = B4[dr + cg + 8];   // contiguous 128B

        float p = dot8(a0, b0, w0, w1) + dot8(a1, b1, w2_, w3);

        // 8-lane group reduction: one chain serves all 4 edges
        p += __shfl_xor_sync(0xffffffffu, p, 1);
        p += __shfl_xor_sync(0xffffffffu, p, 2);
        p += __shfl_xor_sync(0xffffffffu, p, 4);

        if (cg == 0 && e < E2) out[e] = p + b2s;
    }
}

// ---------------------------------------------------------------------------
extern "C" void kernel_launch(void* const* d_in, const int* in_sizes, int n_in,
                              void* d_out, int out_size)
{
    const float *zsrc, *zdst, *W1, *b1, *W2, *b2;
    const void  *ps, *pd, *ns, *nd;
    int zElems, eElems;
    if (in_sizes[0] == 2 * HID * HID) {
        // name-sorted: W1, W2, b1, b2, neg_dst, neg_src, pos_dst, pos_src, z_dst, z_src
        W1 = (const float*)d_in[0];
        W2 = (const float*)d_in[1];
        b1 = (const float*)d_in[2];
        b2 = (const float*)d_in[3];
        nd = d_in[4]; ns = d_in[5];
        pd = d_in[6]; ps = d_in[7];
        zdst = (const float*)d_in[8];
        zsrc = (const float*)d_in[9];
        zElems = in_sizes[8];
        eElems = in_sizes[4];
    } else {
        // dict order: z_src, z_dst, pos_src, pos_dst, neg_src, neg_dst, W1, b1, W2, b2
        zsrc = (const float*)d_in[0];
        zdst = (const float*)d_in[1];
        ps = d_in[2]; pd = d_in[3];
        ns = d_in[4]; nd = d_in[5];
        W1 = (const float*)d_in[6];
        b1 = (const float*)d_in[7];
        W2 = (const float*)d_in[8];
        b2 = (const float*)d_in[9];
        zElems = in_sizes[0];
        eElems = in_sizes[2];
    }

    int nNodes = zElems / HID;
    if (nNodes > MAXN) nNodes = MAXN;
    const int E2 = out_size;   // 2E
    const int Eh = eElems;     // E
    const int nT = (nNodes + 127) / 128;

    const int smem = 2 * 128 * SSTR * (int)sizeof(__half);   // 69632 B
    cudaFuncSetAttribute(gemm_kernel,
                         cudaFuncAttributeMaxDynamicSharedMemorySize, smem);

    gemm_kernel<<<2 * nT, 256, smem>>>(zsrc, zdst, W1, b1, nNodes, nT);
    edge_kernel<<<8192, 256>>>(ps, pd, ns, nd, W2, b2,
                               (float*)d_out, E2, Eh, nNodes);
}

// round 14
// speedup vs baseline: 1.1509x; 1.1509x over previous
#include <cuda_runtime.h>
#include <cuda_fp16.h>
#include <cstdint>

#define HID   128
#define MAXN  100000

// Static device scratch (allocation guards forbid cudaMalloc)
__device__ __half g_Ah[MAXN * HID];   // 25.6 MB  fp16 table A
__device__ __half g_Bh[MAXN * HID];   // 25.6 MB  fp16 table B
__device__ __half g_Wt[2 * HID * HID];// W1^T fp16: [half][n][k]

// ---------------------------------------------------------------------------
// W prep: g_Wt[half][n][k] = W1[half*128 + k][n]   (B operand, col-major k x n)
// One-shot 64KB transpose; paying smem conflicts here once is far cheaper than
// per-CTA in gemm (R13 lesson: -19us vs +4.4us).
// ---------------------------------------------------------------------------
__global__ void wprep_kernel(const float* __restrict__ W1)
{
    int i = blockIdx.x * blockDim.x + threadIdx.x;
    if (i >= 2 * HID * HID) return;
    int half = i >> 14, r = i & 16383, n = r >> 7, k = r & 127;
    g_Wt[i] = __float2half(W1[(half * HID + k) * HID + n]);
}

// ---------------------------------------------------------------------------
// GEMM precompute via mma.sync (HMMA, PTX-portable):
//   half 0: g_Ah[tile] = half( z_src_tile[128x128] @ W1top + b1 )
//   half 1: g_Bh[tile] = half( z_dst_tile[128x128] @ W1bot )
// CTA: 256 thr (8 warps), tile M=128,N=128,K=128.
// Warp tile 32x64: 2 Mtiles x 8 Ntiles of m16n8k16, 8 k-steps.
// smem: sA z-half [128][136], sB Wt [128][136]  (padded, conflict-free).
// ---------------------------------------------------------------------------
#define SSTR 136   // smem row stride in halfs (272 B = 17*16, uint4-aligned)

__global__ __launch_bounds__(256) void gemm_kernel(
    const float* __restrict__ zsrc, const float* __restrict__ zdst,
    const float* __restrict__ b1, int nNodes, int nT)
{
    extern __shared__ __half smem[];
    __half* sA = smem;              // [128][SSTR]
    __half* sB = smem + 128 * SSTR; // [128][SSTR]

    const int half = (blockIdx.x >= (unsigned)nT) ? 1 : 0;
    const int t    = blockIdx.x - half * nT;
    const float* z = half ? zdst : zsrc;
    __half*    tab = half ? g_Bh : g_Ah;

    const int tid  = threadIdx.x;
    const int wid  = tid >> 5;
    const int lane = tid & 31;
    const int grp  = lane >> 2;     // 0..7
    const int tig  = lane & 3;      // 0..3

    // ---- load W^T into sB: [n][k], stride SSTR ----
    {
        const uint4* wb = (const uint4*)(g_Wt + half * HID * HID);
        #pragma unroll 4
        for (int i = tid; i < 2048; i += 256) {       // 2048 uint4 = 16384 halfs
            int n = i >> 4, k0 = (i & 15) * 8;
            *(uint4*)(sB + n * SSTR + k0) = wb[i];
        }
    }
    // ---- load z tile fp32 -> half into sA: [m][k], stride SSTR ----
    {
        const float4* zg = (const float4*)z;
        const size_t base4 = (size_t)t * 4096;        // 128 rows * 32 float4
        const size_t lim4  = (size_t)nNodes * 32;
        #pragma unroll 4
        for (int i = tid; i < 4096; i += 256) {
            float4 v = make_float4(0.f, 0.f, 0.f, 0.f);
            size_t g = base4 + i;
            if (g < lim4) v = zg[g];
            int row = i >> 5, c0 = (i & 31) * 4;
            __half2 h0 = __floats2half2_rn(v.x, v.y);
            __half2 h1 = __floats2half2_rn(v.z, v.w);
            *(uint32_t*)(sA + row * SSTR + c0)     = *(uint32_t*)&h0;
            *(uint32_t*)(sA + row * SSTR + c0 + 2) = *(uint32_t*)&h1;
        }
    }
    __syncthreads();

    const int m_base = (wid >> 1) * 32;   // 4 M-quadrants
    const int n_base = (wid & 1) * 64;    // 2 N-halves

    float c[2][8][4];
    #pragma unroll
    for (int mt = 0; mt < 2; mt++)
        #pragma unroll
        for (int nt = 0; nt < 8; nt++)
            #pragma unroll
            for (int j = 0; j < 4; j++) c[mt][nt][j] = 0.f;

    #pragma unroll
    for (int ks = 0; ks < 8; ks++) {
        const int k0 = ks * 16;
        uint32_t a[2][4], b[8][2];
        #pragma unroll
        for (int mt = 0; mt < 2; mt++) {
            const __half* pr = sA + (m_base + mt * 16 + grp) * SSTR + k0 + tig * 2;
            a[mt][0] = *(const uint32_t*)pr;
            a[mt][1] = *(const uint32_t*)(pr + 8 * SSTR);
            a[mt][2] = *(const uint32_t*)(pr + 8);
            a[mt][3] = *(const uint32_t*)(pr + 8 * SSTR + 8);
        }
        #pragma unroll
        for (int nt = 0; nt < 8; nt++) {
            const __half* pb = sB + (n_base + nt * 8 + grp) * SSTR + k0 + tig * 2;
            b[nt][0] = *(const uint32_t*)pb;
            b[nt][1] = *(const uint32_t*)(pb + 8);
        }
        #pragma unroll
        for (int mt = 0; mt < 2; mt++)
            #pragma unroll
            for (int nt = 0; nt < 8; nt++)
                asm volatile(
                    "mma.sync.aligned.m16n8k16.row.col.f32.f16.f16.f32 "
                    "{%0,%1,%2,%3}, {%4,%5,%6,%7}, {%8,%9}, {%0,%1,%2,%3};"
                    : "+f"(c[mt][nt][0]), "+f"(c[mt][nt][1]),
                      "+f"(c[mt][nt][2]), "+f"(c[mt][nt][3])
                    : "r"(a[mt][0]), "r"(a[mt][1]), "r"(a[mt][2]), "r"(a[mt][3]),
                      "r"(b[nt][0]), "r"(b[nt][1]));
    }
    __syncthreads();    // done reading sA/sB; reuse sA as output stage

    // ---- epilogue: bias (half 0), fp16 pack, stage to sA [m][SSTR] ----
    #pragma unroll
    for (int nt = 0; nt < 8; nt++) {
        const int col = n_base + nt * 8 + tig * 2;
        float bx = 0.f, by = 0.f;
        if (half == 0) { bx = b1[col]; by = b1[col + 1]; }
        #pragma unroll
        for (int mt = 0; mt < 2; mt++) {
            const int r0 = m_base + mt * 16 + grp;
            __half2 h0 = __floats2half2_rn(c[mt][nt][0] + bx, c[mt][nt][1] + by);
            __half2 h1 = __floats2half2_rn(c[mt][nt][2] + bx, c[mt][nt][3] + by);
            *(uint32_t*)(sA + r0 * SSTR + col)       = *(uint32_t*)&h0;
            *(uint32_t*)(sA + (r0 + 8) * SSTR + col) = *(uint32_t*)&h1;
        }
    }
    __syncthreads();

    // ---- coalesced store: 2048 uint4 (128 rows x 16 uint4) ----
    {
        #pragma unroll 4
        for (int i = tid; i < 2048; i += 256) {
            int row = i >> 4, c8 = (i & 15) * 8;
            int node = t * 128 + row;
            if (node < nNodes)
                *(uint4*)(tab + (size_t)node * HID + c8) =
                    *(const uint4*)(sA + row * SSTR + c8);
        }
    }
}

// ---------------------------------------------------------------------------
// Edge kernel (round-11 winner + occupancy bound): warp = 4 edges, 8 LANES
// PER EDGE (eg=lane>>3, cg=lane&7). Lane cg reads uint4 [cg] and [cg+8] of
// the 16-uint4 row: each LDG.128 covers one contiguous 128B segment per edge.
// 3 shfl_xor(1,2,4) serve all 4 edges. __launch_bounds__(256,6) caps regs at
// 42 -> 6 blocks/SM (was 48 regs -> 5 blocks, occ 57.9%).
// ---------------------------------------------------------------------------
__global__ __launch_bounds__(256, 6) void edge_kernel(
    const void* __restrict__ ps, const void* __restrict__ pd,
    const void* __restrict__ ns, const void* __restrict__ nd,
    const float* __restrict__ W2, const float* __restrict__ b2,
    float* __restrict__ out, int E2, int Eh, int nNodes)
{
    __shared__ int sF64;
    if (threadIdx.x == 0) {
        const long long* arrs[4] = {(const long long*)ps, (const long long*)pd,
                                    (const long long*)ns, (const long long*)nd};
        int step = (Eh / 2) / 8;
        if (step < 1) step = 1;
        int ok = 1;
        for (int a = 0; a < 4; a++)
            for (int j = 0; j < 8; j++) {
                long long v = arrs[a][(long long)j * step];
                if (v < 0 || v >= nNodes) ok = 0;
            }
        sF64 = ok;
    }
    __syncthreads();
    const int f64 = sF64;

    const int lane = threadIdx.x & 31;
    const int eg   = lane >> 3;     // which of 4 edges
    const int cg   = lane & 7;      // lane within edge group
    const int gw   = (blockIdx.x * blockDim.x + threadIdx.x) >> 5;
    const int nw   = (gridDim.x * blockDim.x) >> 5;

    // W2 slices: cols 8cg..8cg+7 (low half) and 64+8cg..64+8cg+7 (high half)
    const float4 w0 = ((const float4*)W2)[2 * cg];
    const float4 w1 = ((const float4*)W2)[2 * cg + 1];
    const float4 w2_ = ((const float4*)W2)[16 + 2 * cg];
    const float4 w3 = ((const float4*)W2)[17 + 2 * cg];
    const float  b2s = b2[0];
    const uint4* A4 = (const uint4*)g_Ah;   // row = 16 uint4 (256 B)
    const uint4* B4 = (const uint4*)g_Bh;
    const __half2 hz = __float2half2_rn(0.f);

    auto ldidx = [&](const void* p, int i) -> int {
        long long v = f64 ? ((const long long*)p)[i]
                          : (long long)((const int*)p)[i];
        if (v < 0) v = 0;
        if (v >= nNodes) v = nNodes - 1;
        return (int)v;
    };
    auto dot8 = [&](uint4 a, uint4 b, float4 wA, float4 wB) -> float {
        __half2 s0 = __hmax2(__hadd2(*(__half2*)&a.x, *(__half2*)&b.x), hz);
        __half2 s1 = __hmax2(__hadd2(*(__half2*)&a.y, *(__half2*)&b.y), hz);
        __half2 s2 = __hmax2(__hadd2(*(__half2*)&a.z, *(__half2*)&b.z), hz);
        __half2 s3 = __hmax2(__hadd2(*(__half2*)&a.w, *(__half2*)&b.w), hz);
        float2 f0 = __half22float2(s0);
        float2 f1 = __half22float2(s1);
        float2 f2 = __half22float2(s2);
        float2 f3 = __half22float2(s3);
        return f0.x*wA.x + f0.y*wA.y + f1.x*wA.z + f1.y*wA.w
             + f2.x*wB.x + f2.y*wB.y + f3.x*wB.z + f3.y*wB.w;
    };

    for (int base = gw * 4; base < E2; base += nw * 4) {
        int e = base + eg;
        int s = 0, d = 0;
        if (e < E2) {
            if (e < Eh) { s = ldidx(ps, e);      d = ldidx(pd, e); }
            else        { s = ldidx(ns, e - Eh); d = ldidx(nd, e - Eh); }
        }

        const size_t sr = (size_t)s * 16;
        const size_t dr = (size_t)d * 16;
        uint4 a0 = A4[sr + cg],     b0 = B4[dr + cg];       // contiguous 128B
        uint4 a1 = A4[sr + cg + 8], b1 = B4[dr + cg + 8];   // contiguous 128B

        float p = dot8(a0, b0, w0, w1) + dot8(a1, b1, w2_, w3);

        // 8-lane group reduction: one chain serves all 4 edges
        p += __shfl_xor_sync(0xffffffffu, p, 1);
        p += __shfl_xor_sync(0xffffffffu, p, 2);
        p += __shfl_xor_sync(0xffffffffu, p, 4);

        if (cg == 0 && e < E2) out[e] = p + b2s;
    }
}

// ---------------------------------------------------------------------------
extern "C" void kernel_launch(void* const* d_in, const int* in_sizes, int n_in,
                              void* d_out, int out_size)
{
    const float *zsrc, *zdst, *W1, *b1, *W2, *b2;
    const void  *ps, *pd, *ns, *nd;
    int zElems, eElems;
    if (in_sizes[0] == 2 * HID * HID) {
        // name-sorted: W1, W2, b1, b2, neg_dst, neg_src, pos_dst, pos_src, z_dst, z_src
        W1 = (const float*)d_in[0];
        W2 = (const float*)d_in[1];
        b1 = (const float*)d_in[2];
        b2 = (const float*)d_in[3];
        nd = d_in[4]; ns = d_in[5];
        pd = d_in[6]; ps = d_in[7];
        zdst = (const float*)d_in[8];
        zsrc = (const float*)d_in[9];
        zElems = in_sizes[8];
        eElems = in_sizes[4];
    } else {
        // dict order: z_src, z_dst, pos_src, pos_dst, neg_src, neg_dst, W1, b1, W2, b2
        zsrc = (const float*)d_in[0];
        zdst = (const float*)d_in[1];
        ps = d_in[2]; pd = d_in[3];
        ns = d_in[4]; nd = d_in[5];
        W1 = (const float*)d_in[6];
        b1 = (const float*)d_in[7];
        W2 = (const float*)d_in[8];
        b2 = (const float*)d_in[9];
        zElems = in_sizes[0];
        eElems = in_sizes[2];
    }

    int nNodes = zElems / HID;
    if (nNodes > MAXN) nNodes = MAXN;
    const int E2 = out_size;   // 2E
    const int Eh = eElems;     // E
    const int nT = (nNodes + 127) / 128;

    const int smem = 2 * 128 * SSTR * (int)sizeof(__half);   // 69632 B
    cudaFuncSetAttribute(gemm_kernel,
                         cudaFuncAttributeMaxDynamicSharedMemorySize, smem);

    wprep_kernel<<<128, 256>>>(W1);
    gemm_kernel<<<2 * nT, 256, smem>>>(zsrc, zdst, b1, nNodes, nT);
    edge_kernel<<<8192, 256>>>(ps, pd, ns, nd, W2, b2,
                               (float*)d_out, E2, Eh, nNodes);
}

// round 16
// speedup vs baseline: 1.1841x; 1.0288x over previous
#include <cuda_runtime.h>
#include <cuda_fp16.h>
#include <cstdint>

#define HID   128
#define MAXN  100000

// Static device scratch (allocation guards forbid cudaMalloc)
__device__ __half g_Ah[MAXN * HID];   // 25.6 MB  fp16 table A
__device__ __half g_Bh[MAXN * HID];   // 25.6 MB  fp16 table B
__device__ __half g_Wt[2 * HID * HID];// W1^T fp16: [half][n][k]

// ---------------------------------------------------------------------------
// W prep: g_Wt[half][n][k] = W1[half*128 + k][n]   (B operand, col-major k x n)
// ---------------------------------------------------------------------------
__global__ void wprep_kernel(const float* __restrict__ W1)
{
    int i = blockIdx.x * blockDim.x + threadIdx.x;
    if (i >= 2 * HID * HID) return;
    int half = i >> 14, r = i & 16383, n = r >> 7, k = r & 127;
    g_Wt[i] = __float2half(W1[(half * HID + k) * HID + n]);
}

// ---------------------------------------------------------------------------
// GEMM precompute via mma.sync (HMMA):
//   half 0: g_Ah[tile] = half( z_src_tile[64x128] @ W1top + b1 )
//   half 1: g_Bh[tile] = half( z_dst_tile[64x128] @ W1bot )
// CTA: 128 thr (4 warps), tile M=64,N=128,K=128 — HALF the old CTA so 4 CTAs
// coexist per SM (52.2KB smem, <=128 regs) and their load/compute/store
// phases overlap (old: 2 CTAs/SM, phase-serialized => latency-bound).
// Warp tile 32x64 (2M x 2N warps): 2 Mtiles x 8 Ntiles m16n8k16, 8 k-steps.
// ---------------------------------------------------------------------------
#define SSTR 136   // smem row stride in halfs (272 B = 17*16, uint4-aligned)

__global__ __launch_bounds__(128, 4) void gemm_kernel(
    const float* __restrict__ zsrc, const float* __restrict__ zdst,
    const float* __restrict__ b1, int nNodes, int nT)
{
    extern __shared__ __half smem[];
    __half* sA = smem;              // [64][SSTR]   z tile (reused as out stage)
    __half* sB = smem + 64 * SSTR;  // [128][SSTR]  W^T

    const int half = (blockIdx.x >= (unsigned)nT) ? 1 : 0;
    const int t    = blockIdx.x - half * nT;
    const float* z = half ? zdst : zsrc;
    __half*    tab = half ? g_Bh : g_Ah;

    const int tid  = threadIdx.x;
    const int wid  = tid >> 5;
    const int lane = tid & 31;
    const int grp  = lane >> 2;     // 0..7
    const int tig  = lane & 3;      // 0..3

    // ---- load W^T into sB: [n][k], stride SSTR ----
    {
        const uint4* wb = (const uint4*)(g_Wt + half * HID * HID);
        #pragma unroll 4
        for (int i = tid; i < 2048; i += 128) {       // 2048 uint4 = 16384 halfs
            int n = i >> 4, k0 = (i & 15) * 8;
            *(uint4*)(sB + n * SSTR + k0) = wb[i];
        }
    }
    // ---- load z tile (64 rows) fp32 -> half into sA: [m][k], stride SSTR ----
    {
        const float4* zg = (const float4*)z;
        const size_t base4 = (size_t)t * 2048;        // 64 rows * 32 float4
        const size_t lim4  = (size_t)nNodes * 32;
        #pragma unroll 4
        for (int i = tid; i < 2048; i += 128) {
            float4 v = make_float4(0.f, 0.f, 0.f, 0.f);
            size_t g = base4 + i;
            if (g < lim4) v = zg[g];
            int row = i >> 5, c0 = (i & 31) * 4;
            __half2 h0 = __floats2half2_rn(v.x, v.y);
            __half2 h1 = __floats2half2_rn(v.z, v.w);
            *(uint32_t*)(sA + row * SSTR + c0)     = *(uint32_t*)&h0;
            *(uint32_t*)(sA + row * SSTR + c0 + 2) = *(uint32_t*)&h1;
        }
    }
    __syncthreads();

    const int m_base = (wid >> 1) * 32;   // 2 M-quadrants (0, 32)
    const int n_base = (wid & 1) * 64;    // 2 N-halves

    float c[2][8][4];
    #pragma unroll
    for (int mt = 0; mt < 2; mt++)
        #pragma unroll
        for (int nt = 0; nt < 8; nt++)
            #pragma unroll
            for (int j = 0; j < 4; j++) c[mt][nt][j] = 0.f;

    #pragma unroll
    for (int ks = 0; ks < 8; ks++) {
        const int k0 = ks * 16;
        uint32_t a[2][4], b[8][2];
        #pragma unroll
        for (int mt = 0; mt < 2; mt++) {
            const __half* pr = sA + (m_base + mt * 16 + grp) * SSTR + k0 + tig * 2;
            a[mt][0] = *(const uint32_t*)pr;
            a[mt][1] = *(const uint32_t*)(pr + 8 * SSTR);
            a[mt][2] = *(const uint32_t*)(pr + 8);
            a[mt][3] = *(const uint32_t*)(pr + 8 * SSTR + 8);
        }
        #pragma unroll
        for (int nt = 0; nt < 8; nt++) {
            const __half* pb = sB + (n_base + nt * 8 + grp) * SSTR + k0 + tig * 2;
            b[nt][0] = *(const uint32_t*)pb;
            b[nt][1] = *(const uint32_t*)(pb + 8);
        }
        #pragma unroll
        for (int mt = 0; mt < 2; mt++)
            #pragma unroll
            for (int nt = 0; nt < 8; nt++)
                asm volatile(
                    "mma.sync.aligned.m16n8k16.row.col.f32.f16.f16.f32 "
                    "{%0,%1,%2,%3}, {%4,%5,%6,%7}, {%8,%9}, {%0,%1,%2,%3};"
                    : "+f"(c[mt][nt][0]), "+f"(c[mt][nt][1]),
                      "+f"(c[mt][nt][2]), "+f"(c[mt][nt][3])
                    : "r"(a[mt][0]), "r"(a[mt][1]), "r"(a[mt][2]), "r"(a[mt][3]),
                      "r"(b[nt][0]), "r"(b[nt][1]));
    }
    __syncthreads();    // done reading sA/sB; reuse sA as output stage

    // ---- epilogue: bias (half 0), fp16 pack, stage to sA [m][SSTR] ----
    #pragma unroll
    for (int nt = 0; nt < 8; nt++) {
        const int col = n_base + nt * 8 + tig * 2;
        float bx = 0.f, by = 0.f;
        if (half == 0) { bx = b1[col]; by = b1[col + 1]; }
        #pragma unroll
        for (int mt = 0; mt < 2; mt++) {
            const int r0 = m_base + mt * 16 + grp;
            __half2 h0 = __floats2half2_rn(c[mt][nt][0] + bx, c[mt][nt][1] + by);
            __half2 h1 = __floats2half2_rn(c[mt][nt][2] + bx, c[mt][nt][3] + by);
            *(uint32_t*)(sA + r0 * SSTR + col)       = *(uint32_t*)&h0;
            *(uint32_t*)(sA + (r0 + 8) * SSTR + col) = *(uint32_t*)&h1;
        }
    }
    __syncthreads();

    // ---- coalesced store: 1024 uint4 (64 rows x 16 uint4) ----
    {
        #pragma unroll 4
        for (int i = tid; i < 1024; i += 128) {
            int row = i >> 4, c8 = (i & 15) * 8;
            int node = t * 64 + row;
            if (node < nNodes)
                *(uint4*)(tab + (size_t)node * HID + c8) =
                    *(const uint4*)(sA + row * SSTR + c8);
        }
    }
}

// ---------------------------------------------------------------------------
// Edge kernel (round-14 winner, unchanged): warp = 4 edges, 8 LANES PER EDGE
// (eg=lane>>3, cg=lane&7). Lane cg reads uint4 [cg] and [cg+8] of the
// 16-uint4 row: each LDG.128 covers one contiguous 128B segment per edge.
// 3 shfl_xor(1,2,4) serve all 4 edges. __launch_bounds__(256,6).
// ---------------------------------------------------------------------------
__global__ __launch_bounds__(256, 6) void edge_kernel(
    const void* __restrict__ ps, const void* __restrict__ pd,
    const void* __restrict__ ns, const void* __restrict__ nd,
    const float* __restrict__ W2, const float* __restrict__ b2,
    float* __restrict__ out, int E2, int Eh, int nNodes)
{
    __shared__ int sF64;
    if (threadIdx.x == 0) {
        const long long* arrs[4] = {(const long long*)ps, (const long long*)pd,
                                    (const long long*)ns, (const long long*)nd};
        int step = (Eh / 2) / 8;
        if (step < 1) step = 1;
        int ok = 1;
        for (int a = 0; a < 4; a++)
            for (int j = 0; j < 8; j++) {
                long long v = arrs[a][(long long)j * step];
                if (v < 0 || v >= nNodes) ok = 0;
            }
        sF64 = ok;
    }
    __syncthreads();
    const int f64 = sF64;

    const int lane = threadIdx.x & 31;
    const int eg   = lane >> 3;     // which of 4 edges
    const int cg   = lane & 7;      // lane within edge group
    const int gw   = (blockIdx.x * blockDim.x + threadIdx.x) >> 5;
    const int nw   = (gridDim.x * blockDim.x) >> 5;

    // W2 slices: cols 8cg..8cg+7 (low half) and 64+8cg..64+8cg+7 (high half)
    const float4 w0 = ((const float4*)W2)[2 * cg];
    const float4 w1 = ((const float4*)W2)[2 * cg + 1];
    const float4 w2_ = ((const float4*)W2)[16 + 2 * cg];
    const float4 w3 = ((const float4*)W2)[17 + 2 * cg];
    const float  b2s = b2[0];
    const uint4* A4 = (const uint4*)g_Ah;   // row = 16 uint4 (256 B)
    const uint4* B4 = (const uint4*)g_Bh;
    const __half2 hz = __float2half2_rn(0.f);

    auto ldidx = [&](const void* p, int i) -> int {
        long long v = f64 ? ((const long long*)p)[i]
                          : (long long)((const int*)p)[i];
        if (v < 0) v = 0;
        if (v >= nNodes) v = nNodes - 1;
        return (int)v;
    };
    auto dot8 = [&](uint4 a, uint4 b, float4 wA, float4 wB) -> float {
        __half2 s0 = __hmax2(__hadd2(*(__half2*)&a.x, *(__half2*)&b.x), hz);
        __half2 s1 = __hmax2(__hadd2(*(__half2*)&a.y, *(__half2*)&b.y), hz);
        __half2 s2 = __hmax2(__hadd2(*(__half2*)&a.z, *(__half2*)&b.z), hz);
        __half2 s3 = __hmax2(__hadd2(*(__half2*)&a.w, *(__half2*)&b.w), hz);
        float2 f0 = __half22float2(s0);
        float2 f1 = __half22float2(s1);
        float2 f2 = __half22float2(s2);
        float2 f3 = __half22float2(s3);
        return f0.x*wA.x + f0.y*wA.y + f1.x*wA.z + f1.y*wA.w
             + f2.x*wB.x + f2.y*wB.y + f3.x*wB.z + f3.y*wB.w;
    };

    for (int base = gw * 4; base < E2; base += nw * 4) {
        int e = base + eg;
        int s = 0, d = 0;
        if (e < E2) {
            if (e < Eh) { s = ldidx(ps, e);      d = ldidx(pd, e); }
            else        { s = ldidx(ns, e - Eh); d = ldidx(nd, e - Eh); }
        }

        const size_t sr = (size_t)s * 16;
        const size_t dr = (size_t)d * 16;
        uint4 a0 = A4[sr + cg],     b0 = B4[dr + cg];       // contiguous 128B
        uint4 a1 = A4[sr + cg + 8], b1 = B4[dr + cg + 8];   // contiguous 128B

        float p = dot8(a0, b0, w0, w1) + dot8(a1, b1, w2_, w3);

        // 8-lane group reduction: one chain serves all 4 edges
        p += __shfl_xor_sync(0xffffffffu, p, 1);
        p += __shfl_xor_sync(0xffffffffu, p, 2);
        p += __shfl_xor_sync(0xffffffffu, p, 4);

        if (cg == 0 && e < E2) out[e] = p + b2s;
    }
}

// ---------------------------------------------------------------------------
extern "C" void kernel_launch(void* const* d_in, const int* in_sizes, int n_in,
                              void* d_out, int out_size)
{
    const float *zsrc, *zdst, *W1, *b1, *W2, *b2;
    const void  *ps, *pd, *ns, *nd;
    int zElems, eElems;
    if (in_sizes[0] == 2 * HID * HID) {
        // name-sorted: W1, W2, b1, b2, neg_dst, neg_src, pos_dst, pos_src, z_dst, z_src
        W1 = (const float*)d_in[0];
        W2 = (const float*)d_in[1];
        b1 = (const float*)d_in[2];
        b2 = (const float*)d_in[3];
        nd = d_in[4]; ns = d_in[5];
        pd = d_in[6]; ps = d_in[7];
        zdst = (const float*)d_in[8];
        zsrc = (const float*)d_in[9];
        zElems = in_sizes[8];
        eElems = in_sizes[4];
    } else {
        // dict order: z_src, z_dst, pos_src, pos_dst, neg_src, neg_dst, W1, b1, W2, b2
        zsrc = (const float*)d_in[0];
        zdst = (const float*)d_in[1];
        ps = d_in[2]; pd = d_in[3];
        ns = d_in[4]; nd = d_in[5];
        W1 = (const float*)d_in[6];
        b1 = (const float*)d_in[7];
        W2 = (const float*)d_in[8];
        b2 = (const float*)d_in[9];
        zElems = in_sizes[0];
        eElems = in_sizes[2];
    }

    int nNodes = zElems / HID;
    if (nNodes > MAXN) nNodes = MAXN;
    const int E2 = out_size;   // 2E
    const int Eh = eElems;     // E
    const int nT = (nNodes + 63) / 64;   // M=64 tiles now

    const int smem = (64 + 128) * SSTR * (int)sizeof(__half);   // 52224 B
    cudaFuncSetAttribute(gemm_kernel,
                         cudaFuncAttributeMaxDynamicSharedMemorySize, smem);

    wprep_kernel<<<128, 256>>>(W1);
    gemm_kernel<<<2 * nT, 128, smem>>>(zsrc, zdst, b1, nNodes, nT);
    edge_kernel<<<8192, 256>>>(ps, pd, ns, nd, W2, b2,
                               (float*)d_out, E2, Eh, nNodes);
}

// round 17
// speedup vs baseline: 1.2261x; 1.0355x over previous
#include <cuda_runtime.h>
#include <cuda_fp16.h>
#include <cstdint>

#define HID   128
#define MAXN  100000

// Static device scratch (allocation guards forbid cudaMalloc)
__device__ __half g_Ah[MAXN * HID];   // 25.6 MB  fp16 table A
__device__ __half g_Bh[MAXN * HID];   // 25.6 MB  fp16 table B
__device__ __half g_Wt[2 * HID * HID];// W1^T fp16: [half][n][k]

// ---------------------------------------------------------------------------
// W prep v2: coalesced 32x32 smem-tile transpose.
//   g_Wt[half][n][k] = W1[half*128 + k][n]
// grid = 32 blocks (2 halves x 4x4 tiles), 256 threads.
// Reads coalesced f32, smem stride-33 (conflict-free), writes coalesced f16.
// ---------------------------------------------------------------------------
__global__ void wprep_kernel(const float* __restrict__ W1)
{
    __shared__ float tile[32][33];
    const int bid  = blockIdx.x;
    const int half = bid >> 4;
    const int tk   = (bid >> 2) & 3;   // k-tile
    const int tn   = bid & 3;          // n-tile
    const int tid  = threadIdx.x;
    const int r    = tid >> 5;         // 0..7
    const int c    = tid & 31;

    #pragma unroll
    for (int p = 0; p < 4; p++) {
        int k = p * 8 + r;
        tile[k][c] = W1[(half * 128 + tk * 32 + k) * 128 + tn * 32 + c];
    }
    __syncthreads();
    #pragma unroll
    for (int p = 0; p < 4; p++) {
        int n = p * 8 + r;
        g_Wt[half * 16384 + (tn * 32 + n) * 128 + tk * 32 + c] =
            __float2half(tile[c][n]);
    }
}

// ---------------------------------------------------------------------------
// GEMM precompute via mma.sync (HMMA):
//   half 0: g_Ah = half( z_src @ W1top + b1 );  half 1: g_Bh = half( z_dst @ W1bot )
// CTA: 128 thr (4 warps), tile M=64,N=128,K=128; 4 CTAs/SM (52.2KB smem).
// NEW: each CTA processes 2 consecutive tiles, loading the 32KB W blob ONCE
// (halves the per-tile load phase; W stays smem-resident across both tiles).
// Warp tile 32x64 (2M x 2N warps): 2 Mtiles x 8 Ntiles m16n8k16, 8 k-steps.
// ---------------------------------------------------------------------------
#define SSTR 136   // smem row stride in halfs (272 B = 17*16, uint4-aligned)

__global__ __launch_bounds__(128, 4) void gemm_kernel(
    const float* __restrict__ zsrc, const float* __restrict__ zdst,
    const float* __restrict__ b1, int nNodes, int nT, int nB)
{
    extern __shared__ __half smem[];
    __half* sA = smem;              // [64][SSTR]   z tile (reused as out stage)
    __half* sB = smem + 64 * SSTR;  // [128][SSTR]  W^T

    const int half = (blockIdx.x >= (unsigned)nB) ? 1 : 0;
    const int bb   = blockIdx.x - half * nB;
    const float* z = half ? zdst : zsrc;
    __half*    tab = half ? g_Bh : g_Ah;

    const int tid  = threadIdx.x;
    const int wid  = tid >> 5;
    const int lane = tid & 31;
    const int grp  = lane >> 2;     // 0..7
    const int tig  = lane & 3;      // 0..3

    // ---- load W^T into sB once: [n][k], stride SSTR ----
    {
        const uint4* wb = (const uint4*)(g_Wt + half * HID * HID);
        #pragma unroll 4
        for (int i = tid; i < 2048; i += 128) {       // 2048 uint4 = 16384 halfs
            int n = i >> 4, k0 = (i & 15) * 8;
            *(uint4*)(sB + n * SSTR + k0) = wb[i];
        }
    }

    const int m_base = (wid >> 1) * 32;   // 2 M-quadrants (0, 32)
    const int n_base = (wid & 1) * 64;    // 2 N-halves

    #pragma unroll 1
    for (int tt = 0; tt < 2; tt++) {
        const int t = bb * 2 + tt;
        if (t >= nT) break;
        if (tt) __syncthreads();    // sA store of prev tile fully read

        // ---- load z tile (64 rows) fp32 -> half into sA ----
        {
            const float4* zg = (const float4*)z;
            const size_t base4 = (size_t)t * 2048;    // 64 rows * 32 float4
            const size_t lim4  = (size_t)nNodes * 32;
            #pragma unroll 4
            for (int i = tid; i < 2048; i += 128) {
                float4 v = make_float4(0.f, 0.f, 0.f, 0.f);
                size_t g = base4 + i;
                if (g < lim4) v = zg[g];
                int row = i >> 5, c0 = (i & 31) * 4;
                __half2 h0 = __floats2half2_rn(v.x, v.y);
                __half2 h1 = __floats2half2_rn(v.z, v.w);
                *(uint32_t*)(sA + row * SSTR + c0)     = *(uint32_t*)&h0;
                *(uint32_t*)(sA + row * SSTR + c0 + 2) = *(uint32_t*)&h1;
            }
        }
        __syncthreads();

        float c[2][8][4];
        #pragma unroll
        for (int mt = 0; mt < 2; mt++)
            #pragma unroll
            for (int nt = 0; nt < 8; nt++)
                #pragma unroll
                for (int j = 0; j < 4; j++) c[mt][nt][j] = 0.f;

        #pragma unroll
        for (int ks = 0; ks < 8; ks++) {
            const int k0 = ks * 16;
            uint32_t a[2][4], b[8][2];
            #pragma unroll
            for (int mt = 0; mt < 2; mt++) {
                const __half* pr = sA + (m_base + mt * 16 + grp) * SSTR + k0 + tig * 2;
                a[mt][0] = *(const uint32_t*)pr;
                a[mt][1] = *(const uint32_t*)(pr + 8 * SSTR);
                a[mt][2] = *(const uint32_t*)(pr + 8);
                a[mt][3] = *(const uint32_t*)(pr + 8 * SSTR + 8);
            }
            #pragma unroll
            for (int nt = 0; nt < 8; nt++) {
                const __half* pb = sB + (n_base + nt * 8 + grp) * SSTR + k0 + tig * 2;
                b[nt][0] = *(const uint32_t*)pb;
                b[nt][1] = *(const uint32_t*)(pb + 8);
            }
            #pragma unroll
            for (int mt = 0; mt < 2; mt++)
                #pragma unroll
                for (int nt = 0; nt < 8; nt++)
                    asm volatile(
                        "mma.sync.aligned.m16n8k16.row.col.f32.f16.f16.f32 "
                        "{%0,%1,%2,%3}, {%4,%5,%6,%7}, {%8,%9}, {%0,%1,%2,%3};"
                        : "+f"(c[mt][nt][0]), "+f"(c[mt][nt][1]),
                          "+f"(c[mt][nt][2]), "+f"(c[mt][nt][3])
                        : "r"(a[mt][0]), "r"(a[mt][1]), "r"(a[mt][2]), "r"(a[mt][3]),
                          "r"(b[nt][0]), "r"(b[nt][1]));
        }
        __syncthreads();    // done reading sA; reuse as output stage

        // ---- epilogue: bias (half 0), fp16 pack, stage to sA ----
        #pragma unroll
        for (int nt = 0; nt < 8; nt++) {
            const int col = n_base + nt * 8 + tig * 2;
            float bx = 0.f, by = 0.f;
            if (half == 0) { bx = b1[col]; by = b1[col + 1]; }
            #pragma unroll
            for (int mt = 0; mt < 2; mt++) {
                const int r0 = m_base + mt * 16 + grp;
                __half2 h0 = __floats2half2_rn(c[mt][nt][0] + bx, c[mt][nt][1] + by);
                __half2 h1 = __floats2half2_rn(c[mt][nt][2] + bx, c[mt][nt][3] + by);
                *(uint32_t*)(sA + r0 * SSTR + col)       = *(uint32_t*)&h0;
                *(uint32_t*)(sA + (r0 + 8) * SSTR + col) = *(uint32_t*)&h1;
            }
        }
        __syncthreads();

        // ---- coalesced store: 1024 uint4 (64 rows x 16 uint4) ----
        #pragma unroll 4
        for (int i = tid; i < 1024; i += 128) {
            int row = i >> 4, c8 = (i & 15) * 8;
            int node = t * 64 + row;
            if (node < nNodes)
                *(uint4*)(tab + (size_t)node * HID + c8) =
                    *(const uint4*)(sA + row * SSTR + c8);
        }
    }
}

// ---------------------------------------------------------------------------
// Edge kernel (round-14 winner, unchanged): warp = 4 edges, 8 LANES PER EDGE
// (eg=lane>>3, cg=lane&7). Lane cg reads uint4 [cg] and [cg+8] of the
// 16-uint4 row: each LDG.128 covers one contiguous 128B segment per edge.
// 3 shfl_xor(1,2,4) serve all 4 edges. __launch_bounds__(256,6).
// ---------------------------------------------------------------------------
__global__ __launch_bounds__(256, 6) void edge_kernel(
    const void* __restrict__ ps, const void* __restrict__ pd,
    const void* __restrict__ ns, const void* __restrict__ nd,
    const float* __restrict__ W2, const float* __restrict__ b2,
    float* __restrict__ out, int E2, int Eh, int nNodes)
{
    __shared__ int sF64;
    if (threadIdx.x == 0) {
        const long long* arrs[4] = {(const long long*)ps, (const long long*)pd,
                                    (const long long*)ns, (const long long*)nd};
        int step = (Eh / 2) / 8;
        if (step < 1) step = 1;
        int ok = 1;
        for (int a = 0; a < 4; a++)
            for (int j = 0; j < 8; j++) {
                long long v = arrs[a][(long long)j * step];
                if (v < 0 || v >= nNodes) ok = 0;
            }
        sF64 = ok;
    }
    __syncthreads();
    const int f64 = sF64;

    const int lane = threadIdx.x & 31;
    const int eg   = lane >> 3;     // which of 4 edges
    const int cg   = lane & 7;      // lane within edge group
    const int gw   = (blockIdx.x * blockDim.x + threadIdx.x) >> 5;
    const int nw   = (gridDim.x * blockDim.x) >> 5;

    // W2 slices: cols 8cg..8cg+7 (low half) and 64+8cg..64+8cg+7 (high half)
    const float4 w0 = ((const float4*)W2)[2 * cg];
    const float4 w1 = ((const float4*)W2)[2 * cg + 1];
    const float4 w2_ = ((const float4*)W2)[16 + 2 * cg];
    const float4 w3 = ((const float4*)W2)[17 + 2 * cg];
    const float  b2s = b2[0];
    const uint4* A4 = (const uint4*)g_Ah;   // row = 16 uint4 (256 B)
    const uint4* B4 = (const uint4*)g_Bh;
    const __half2 hz = __float2half2_rn(0.f);

    auto ldidx = [&](const void* p, int i) -> int {
        long long v = f64 ? ((const long long*)p)[i]
                          : (long long)((const int*)p)[i];
        if (v < 0) v = 0;
        if (v >= nNodes) v = nNodes - 1;
        return (int)v;
    };
    auto dot8 = [&](uint4 a, uint4 b, float4 wA, float4 wB) -> float {
        __half2 s0 = __hmax2(__hadd2(*(__half2*)&a.x, *(__half2*)&b.x), hz);
        __half2 s1 = __hmax2(__hadd2(*(__half2*)&a.y, *(__half2*)&b.y), hz);
        __half2 s2 = __hmax2(__hadd2(*(__half2*)&a.z, *(__half2*)&b.z), hz);
        __half2 s3 = __hmax2(__hadd2(*(__half2*)&a.w, *(__half2*)&b.w), hz);
        float2 f0 = __half22float2(s0);
        float2 f1 = __half22float2(s1);
        float2 f2 = __half22float2(s2);
        float2 f3 = __half22float2(s3);
        return f0.x*wA.x + f0.y*wA.y + f1.x*wA.z + f1.y*wA.w
             + f2.x*wB.x + f2.y*wB.y + f3.x*wB.z + f3.y*wB.w;
    };

    for (int base = gw * 4; base < E2; base += nw * 4) {
        int e = base + eg;
        int s = 0, d = 0;
        if (e < E2) {
            if (e < Eh) { s = ldidx(ps, e);      d = ldidx(pd, e); }
            else        { s = ldidx(ns, e - Eh); d = ldidx(nd, e - Eh); }
        }

        const size_t sr = (size_t)s * 16;
        const size_t dr = (size_t)d * 16;
        uint4 a0 = A4[sr + cg],     b0 = B4[dr + cg];       // contiguous 128B
        uint4 a1 = A4[sr + cg + 8], b1 = B4[dr + cg + 8];   // contiguous 128B

        float p = dot8(a0, b0, w0, w1) + dot8(a1, b1, w2_, w3);

        // 8-lane group reduction: one chain serves all 4 edges
        p += __shfl_xor_sync(0xffffffffu, p, 1);
        p += __shfl_xor_sync(0xffffffffu, p, 2);
        p += __shfl_xor_sync(0xffffffffu, p, 4);

        if (cg == 0 && e < E2) out[e] = p + b2s;
    }
}

// ---------------------------------------------------------------------------
extern "C" void kernel_launch(void* const* d_in, const int* in_sizes, int n_in,
                              void* d_out, int out_size)
{
    const float *zsrc, *zdst, *W1, *b1, *W2, *b2;
    const void  *ps, *pd, *ns, *nd;
    int zElems, eElems;
    if (in_sizes[0] == 2 * HID * HID) {
        // name-sorted: W1, W2, b1, b2, neg_dst, neg_src, pos_dst, pos_src, z_dst, z_src
        W1 = (const float*)d_in[0];
        W2 = (const float*)d_in[1];
        b1 = (const float*)d_in[2];
        b2 = (const float*)d_in[3];
        nd = d_in[4]; ns = d_in[5];
        pd = d_in[6]; ps = d_in[7];
        zdst = (const float*)d_in[8];
        zsrc = (const float*)d_in[9];
        zElems = in_sizes[8];
        eElems = in_sizes[4];
    } else {
        // dict order: z_src, z_dst, pos_src, pos_dst, neg_src, neg_dst, W1, b1, W2, b2
        zsrc = (const float*)d_in[0];
        zdst = (const float*)d_in[1];
        ps = d_in[2]; pd = d_in[3];
        ns = d_in[4]; nd = d_in[5];
        W1 = (const float*)d_in[6];
        b1 = (const float*)d_in[7];
        W2 = (const float*)d_in[8];
        b2 = (const float*)d_in[9];
        zElems = in_sizes[0];
        eElems = in_sizes[2];
    }

    int nNodes = zElems / HID;
    if (nNodes > MAXN) nNodes = MAXN;
    const int E2 = out_size;   // 2E
    const int Eh = eElems;     // E
    const int nT = (nNodes + 63) / 64;   // M=64 tiles
    const int nB = (nT + 1) / 2;         // 2 tiles per CTA

    const int smem = (64 + 128) * SSTR * (int)sizeof(__half);   // 52224 B
    cudaFuncSetAttribute(gemm_kernel,
                         cudaFuncAttributeMaxDynamicSharedMemorySize, smem);

    wprep_kernel<<<32, 256>>>(W1);
    gemm_kernel<<<2 * nB, 128, smem>>>(zsrc, zdst, b1, nNodes, nT, nB);
    edge_kernel<<<8192, 256>>>(ps, pd, ns, nd, W2, b2,
                               (float*)d_out, E2, Eh, nNodes);
}